// round 11
// baseline (speedup 1.0000x reference)
#include <cuda_runtime.h>
#include <cstdint>
#include <math.h>

#define BB 64
#define HH 256
#define WW 256
#define HWSZ 65536
#define NTOT 4194304

#define OFF_UIFFT 0
#define OFF_ABS   8388608
#define OFF_MASK  12582912
#define OFF_FFT   16777216
#define OFF_UK    25165824

typedef unsigned long long u64;

__device__ double g_partial[64];
__device__ float  g_r, g_beta;
__device__ int    g_le;
__device__ float  g_prob2[HWSZ];   // holds prob1 (pre-rescale)
// packed twiddle tables: t1rr=(wr,wr) shared by both dirs; t1ii=(-wi,wi) per dir
__device__ u64   g_t1rr[256], g_t1iiF[256], g_t1iiI[256];
__device__ float g_t2rF[256], g_t2iF[256], g_t2rI[256], g_t2iI[256];

// ---------------- packed f32x2 helpers ----------------
__device__ __forceinline__ u64 pk(float x, float y) {
    u64 r; asm("mov.b64 %0, {%1, %2};" : "=l"(r) : "f"(x), "f"(y)); return r;
}
__device__ __forceinline__ void upk(u64 v, float& x, float& y) {
    asm("mov.b64 {%0, %1}, %2;" : "=f"(x), "=f"(y) : "l"(v));
}
__device__ __forceinline__ u64 f2add(u64 a, u64 b) {
    u64 r; asm("add.rn.f32x2 %0, %1, %2;" : "=l"(r) : "l"(a), "l"(b)); return r;
}
__device__ __forceinline__ u64 f2mul(u64 a, u64 b) {
    u64 r; asm("mul.rn.f32x2 %0, %1, %2;" : "=l"(r) : "l"(a), "l"(b)); return r;
}
__device__ __forceinline__ u64 f2fma(u64 a, u64 b, u64 c) {
    u64 r; asm("fma.rn.f32x2 %0, %1, %2, %3;" : "=l"(r) : "l"(a), "l"(b), "l"(c)); return r;
}
__device__ __forceinline__ u64 f2swap(u64 v) {
    float x, y; upk(v, x, y); return pk(y, x);
}

// ---------------- Threefry-2x32-20 (exact jax) ----------------
__host__ __device__ __forceinline__ unsigned rotl32(unsigned v, int d) {
    return (v << d) | (v >> (32 - d));
}

__host__ __device__ __forceinline__ void threefry2x32(unsigned k0, unsigned k1,
                                                      unsigned c0, unsigned c1,
                                                      unsigned& o0, unsigned& o1) {
    unsigned ks2 = k0 ^ k1 ^ 0x1BD11BDAu;
    unsigned x0 = c0 + k0;
    unsigned x1 = c1 + k1;
#define TF_R(r) { x0 += x1; x1 = rotl32(x1, r); x1 ^= x0; }
    TF_R(13) TF_R(15) TF_R(26) TF_R(6)
    x0 += k1;  x1 += ks2 + 1u;
    TF_R(17) TF_R(29) TF_R(16) TF_R(24)
    x0 += ks2; x1 += k0 + 2u;
    TF_R(13) TF_R(15) TF_R(26) TF_R(6)
    x0 += k0;  x1 += k1 + 3u;
    TF_R(17) TF_R(29) TF_R(16) TF_R(24)
    x0 += k1;  x1 += ks2 + 4u;
    TF_R(13) TF_R(15) TF_R(26) TF_R(6)
    x0 += ks2; x1 += k0 + 5u;
#undef TF_R
    o0 = x0; o1 = x1;
}

// ---------------- XLA-exact sigmoid pieces ----------------
__device__ __forceinline__ float tanh_xla(float x) {
    float ax = fabsf(x);
    float xc = fminf(fmaxf(x, -7.90531110763549805f), 7.90531110763549805f);
    float x2 = __fmul_rn(xc, xc);
    float p = -2.76076847742355e-16f;
    p = fmaf(p, x2, 2.00018790482477e-13f);
    p = fmaf(p, x2, -8.60467152213735e-11f);
    p = fmaf(p, x2, 5.12229709037114e-08f);
    p = fmaf(p, x2, 1.48572235717979e-05f);
    p = fmaf(p, x2, 6.37261928875436e-04f);
    p = fmaf(p, x2, 4.89352455891786e-03f);
    p = __fmul_rn(p, xc);
    float q = 1.19825839466702e-06f;
    q = fmaf(q, x2, 1.18534705686654e-04f);
    q = fmaf(q, x2, 2.26843463243900e-03f);
    q = fmaf(q, x2, 4.89352518554385e-03f);
    float r = __fdiv_rn(p, q);
    return (ax < 0.0004f) ? x : r;
}

__device__ __forceinline__ float prob1_of(float wv) {
    float arg = __fmul_rn(0.5f, __fmul_rn(5.0f, wv));
    float t = tanh_xla(arg);
    return __fadd_rn(0.5f, __fmul_rn(0.5f, t));
}

// ---------------- reduction: prob1 -> g_prob2, partial sums ----------------
__global__ void k_reduce(const float* __restrict__ w) {
    __shared__ double sd[256];
    int t = threadIdx.x;
    int i0 = (blockIdx.x * 256 + t) * 4;
    float4 wq = *reinterpret_cast<const float4*>(w + i0);
    float p0 = prob1_of(wq.x), p1 = prob1_of(wq.y);
    float p2 = prob1_of(wq.z), p3 = prob1_of(wq.w);
    *reinterpret_cast<float4*>(g_prob2 + i0) = make_float4(p0, p1, p2, p3);
    sd[t] = (double)p0 + (double)p1 + (double)p2 + (double)p3;
    __syncthreads();
    for (int s = 128; s > 0; s >>= 1) {
        if (t < s) sd[t] += sd[t + s];
        __syncthreads();
    }
    if (t == 0) g_partial[blockIdx.x] = sd[0];
}

// final sum + constants + packed twiddle tables
__global__ void k_final() {
    __shared__ double sd[64];
    int t = threadIdx.x;
    if (t < 64) sd[t] = g_partial[t];
    {
        int c = t >> 5, l = t & 31;
        float s1, c1;
        sincospif((float)(l * c) / 128.0f, &s1, &c1);
        g_t1rr[t]  = pk(c1, c1);
        g_t1iiF[t] = pk(s1, -s1);    // fwd: wi=-s1 -> (-wi, wi)
        g_t1iiI[t] = pk(-s1, s1);    // inv: wi=+s1
        int d0 = ((l >> 4) & 1) + (((l >> 3) & 1) << 1);
        float s2, c2;
        sincospif((float)(c * d0) / 16.0f, &s2, &c2);
        g_t2rF[t] = c2; g_t2iF[t] = -s2;
        const float sc = 1.0f / 256.0f;
        g_t2rI[t] = c2 * sc; g_t2iI[t] = s2 * sc;
    }
    __syncthreads();
    for (int s = 32; s > 0; s >>= 1) {
        if (t < s) sd[t] += sd[t + s];
        __syncthreads();
    }
    if (t == 0) {
        float xbar = (float)(sd[0] / 65536.0);
        g_r    = __fdiv_rn(0.125f, xbar);
        g_beta = __fdiv_rn(0.875f, __fsub_rn(1.0f, xbar));
        g_le   = (g_r < 1.0f) ? 1 : 0;
    }
}

// ---------------- packed four-step FFT ----------------
// SWZ2: row swizzle injecting bit4 into bit3 for 64-bit bank safety
#define SWZ2(row) ((row) ^ ((row) >> 5) ^ (((row) & 16) >> 1))
#define HSQ 0.70710678118654752f
__device__ __constant__ int BRC[8] = {0, 4, 2, 6, 1, 5, 3, 7};

// 8-pt DIF in packed registers; output reg j = X[brev3(j)]
template<int SIGN>
__device__ __forceinline__ void radix8p(u64 (&v)[8]) {
    const float E = (float)SIGN;
    const u64 NEG1 = pk(-1.0f, -1.0f);
    const u64 JE   = pk(-E, E);          // multiply by (0, E)
    const u64 Hp   = pk(HSQ, HSQ);
    const u64 Hn   = pk(-HSQ, -HSQ);
    const u64 W1   = pk(-E * HSQ, E * HSQ);
    u64 t;
    // stage 1 (dist 4): diff then twiddle w8^n
    t = f2fma(v[4], NEG1, v[0]); v[0] = f2add(v[0], v[4]); v[4] = t;
    t = f2fma(v[5], NEG1, v[1]); v[1] = f2add(v[1], v[5]);
    v[5] = f2fma(f2swap(t), W1, f2mul(t, Hp));
    t = f2fma(v[6], NEG1, v[2]); v[2] = f2add(v[2], v[6]);
    v[6] = f2mul(f2swap(t), JE);
    t = f2fma(v[7], NEG1, v[3]); v[3] = f2add(v[3], v[7]);
    v[7] = f2fma(f2swap(t), W1, f2mul(t, Hn));
    // stage 2 (dist 2)
    t = f2fma(v[2], NEG1, v[0]); v[0] = f2add(v[0], v[2]); v[2] = t;
    t = f2fma(v[3], NEG1, v[1]); v[1] = f2add(v[1], v[3]); v[3] = f2mul(f2swap(t), JE);
    t = f2fma(v[6], NEG1, v[4]); v[4] = f2add(v[4], v[6]); v[6] = t;
    t = f2fma(v[7], NEG1, v[5]); v[5] = f2add(v[5], v[7]); v[7] = f2mul(f2swap(t), JE);
    // stage 3 (dist 1)
    t = f2fma(v[1], NEG1, v[0]); v[0] = f2add(v[0], v[1]); v[1] = t;
    t = f2fma(v[3], NEG1, v[2]); v[2] = f2add(v[2], v[3]); v[3] = t;
    t = f2fma(v[5], NEG1, v[4]); v[4] = f2add(v[4], v[5]); v[5] = t;
    t = f2fma(v[7], NEG1, v[6]); v[6] = f2add(v[6], v[7]); v[7] = t;
}

// 4-pt DIF across lane bits 3/4 (scalar; shuffles are 32-bit)
template<int SIGN>
__device__ __forceinline__ void radix4_lanes(float (&zr)[8], float (&zi)[8], int lane) {
    const float E = (float)SIGN;
    float s16 = (lane & 16) ? -1.0f : 1.0f;
    float s8  = (lane & 8)  ? -1.0f : 1.0f;
    bool tw = ((lane & 24) == 24);
#pragma unroll
    for (int r = 0; r < 8; r++) {
        float pr = __shfl_xor_sync(0xffffffffu, zr[r], 16);
        float pi = __shfl_xor_sync(0xffffffffu, zi[r], 16);
        float ar = fmaf(s16, zr[r], pr);
        float ai = fmaf(s16, zi[r], pi);
        if (tw) { float tt = ar; ar = -E * ai; ai = E * tt; }
        float qr = __shfl_xor_sync(0xffffffffu, ar, 8);
        float qi = __shfl_xor_sync(0xffffffffu, ai, 8);
        zr[r] = fmaf(s8, ar, qr);
        zi[r] = fmaf(s8, ai, qi);
    }
}

// full 256-pt FFT, packed. buf = column base (u64 units), addressing buf[SWZ2(row)^xc].
// input v[j] = x[lane + 32j]; output v[j] = X[(lane&7) + 8*e0(lane) + 32*brev3(j)].
template<int SIGN>
__device__ __forceinline__ void fft256p(u64 (&v)[8], int lane, u64* buf, int xc,
                                        const u64* __restrict__ t1rr,
                                        const u64* __restrict__ t1ii,
                                        const float* __restrict__ t2r,
                                        const float* __restrict__ t2i) {
    radix8p<SIGN>(v);
#pragma unroll
    for (int j = 0; j < 8; j++) {
        int c = BRC[j];
        u64 z = v[j];
        z = f2fma(f2swap(z), t1ii[c * 32 + lane], f2mul(z, t1rr[c * 32 + lane]));
        buf[SWZ2(lane + 32 * c) ^ xc] = z;
    }
    __syncwarp();
    float zr[8], zi[8];
#pragma unroll
    for (int r = 0; r < 8; r++) {
        u64 z = buf[SWZ2(r + 8 * (lane >> 3) + 32 * (lane & 7)) ^ xc];
        upk(z, zr[r], zi[r]);
    }
    radix4_lanes<SIGN>(zr, zi, lane);
#pragma unroll
    for (int r = 0; r < 8; r++) {
        float wr = t2r[r * 32 + lane], wi = t2i[r * 32 + lane];
        float nr = zr[r] * wr - zi[r] * wi;
        float ni = zr[r] * wi + zi[r] * wr;
        v[r] = pk(nr, ni);
    }
    radix8p<SIGN>(v);
}

// ------- row forward FFT + fused mask generation -------
__global__ void k_row_fwd(const float* __restrict__ x, float* __restrict__ fftreg,
                          float* __restrict__ maskreg, unsigned sk0, unsigned sk1) {
    __shared__ u64 scr[8 * 256];
    __shared__ u64 s_t1rr[256], s_t1ii[256];
    __shared__ float s_t2r[256], s_t2i[256];
    int t = threadIdx.x, lane = t & 31, wp = t >> 5;
    s_t1rr[t] = g_t1rr[t]; s_t1ii[t] = g_t1iiF[t];
    s_t2r[t] = g_t2rF[t];  s_t2i[t] = g_t2iF[t];
    int bx = blockIdx.x, b = blockIdx.y;
    // mask generation for this CTA's 2048 elements
    {
        float rr = g_r, bb = g_beta;
        int le = g_le;
        float* mk = maskreg + (size_t)b * HWSZ;
#pragma unroll
        for (int pass = 0; pass < 2; pass++) {
            int hw = bx * 2048 + pass * 1024 + t * 4;
            float4 p1 = *reinterpret_cast<const float4*>(g_prob2 + hw);
            float pv[4] = {p1.x, p1.y, p1.z, p1.w};
            unsigned base = (unsigned)(b * HWSZ + hw);
            float mm[4];
#pragma unroll
            for (int q = 0; q < 4; q++) {
                float p2 = le ? __fmul_rn(pv[q], rr)
                              : __fsub_rn(1.0f, __fmul_rn(__fsub_rn(1.0f, pv[q]), bb));
                unsigned o0, o1;
                threefry2x32(sk0, sk1, 0u, base + (unsigned)q, o0, o1);
                unsigned bits = o0 ^ o1;
                float u = __uint_as_float((bits >> 9) | 0x3f800000u) - 1.0f;
                mm[q] = (p2 > u) ? 1.0f : 0.0f;
            }
            *reinterpret_cast<float4*>(mk + hw) = make_float4(mm[0], mm[1], mm[2], mm[3]);
        }
    }
    __syncthreads();
    int row = bx * 8 + wp;
    const float* xp = x + (size_t)b * HWSZ + (size_t)row * WW;
    u64 v[8];
#pragma unroll
    for (int j = 0; j < 8; j++) v[j] = pk(xp[lane + 32 * j], 0.0f);
    fft256p<-1>(v, lane, scr + wp * 256, 0, s_t1rr, s_t1ii, s_t2r, s_t2i);
    int d0l = ((lane >> 4) & 1) + (((lane >> 3) & 1) << 1);
    float* fr = fftreg + (size_t)b * 2 * HWSZ + (size_t)row * WW;
    float* fi = fr + HWSZ;
#pragma unroll
    for (int j = 0; j < 8; j++) {
        int n = (lane & 7) + 8 * d0l + 32 * BRC[j];
        float a, bb2; upk(v[j], a, bb2);
        fr[n] = a; fi[n] = bb2;
    }
}

// ---------- fused column kernel: packed 32-col tile, 512 threads ----------
#define CCP2 288
#define XC(c) ((((c) >> 2) & 7) << 1)
#define SMA(c, row) ((c) * CCP2 + (SWZ2(row) ^ XC(c)))

__global__ void __launch_bounds__(512, 2)
k_col(float* __restrict__ fftreg, const float* __restrict__ maskreg,
      float* __restrict__ ukreg, float* __restrict__ stage) {
    extern __shared__ u64 sm[];
    u64* tile   = sm;                  // 32*288 u64
    u64* t1rr   = sm + 32 * CCP2;      // 256
    u64* t1iiF  = t1rr + 256;
    u64* t1iiI  = t1iiF + 256;
    float* fsc  = (float*)(t1iiI + 256);
    float* t2rF = fsc;        float* t2iF = fsc + 256;
    float* t2rI = fsc + 512;  float* t2iI = fsc + 768;
    int t = threadIdx.x, lane = t & 31, wp = t >> 5;
    int b = blockIdx.y, c0 = blockIdx.x * 32;
    int cg = t & 7, rloc = t >> 3;
    float* fr = fftreg + (size_t)b * 2 * HWSZ;
    float* fi = fr + HWSZ;

    if (t < 256) {
        t1rr[t] = g_t1rr[t]; t1iiF[t] = g_t1iiF[t]; t1iiI[t] = g_t1iiI[t];
        t2rF[t] = g_t2rF[t]; t2iF[t] = g_t2iF[t];
        t2rI[t] = g_t2rI[t]; t2iI[t] = g_t2iI[t];
    }

    // load 256x32 tile, float4 gmem reads, packed STS64
#pragma unroll
    for (int k = 0; k < 4; k++) {
        int row = k * 64 + rloc;
        int g = row * WW + c0 + cg * 4;
        float4 vre = *reinterpret_cast<const float4*>(fr + g);
        float4 vim = *reinterpret_cast<const float4*>(fi + g);
        int c = cg * 4;
        tile[SMA(c, row)]     = pk(vre.x, vim.x);
        tile[SMA(c + 1, row)] = pk(vre.y, vim.y);
        tile[SMA(c + 2, row)] = pk(vre.z, vim.z);
        tile[SMA(c + 3, row)] = pk(vre.w, vim.w);
    }
    __syncthreads();

    int d0l = ((lane >> 4) & 1) + (((lane >> 3) & 1) << 1);
    // forward FFTs: 2 columns per warp
#pragma unroll 1
    for (int j2 = 0; j2 < 2; j2++) {
        int cc = wp * 2 + j2;
        u64* buf = tile + cc * CCP2;
        int xc = XC(cc);
        u64 v[8];
#pragma unroll
        for (int j = 0; j < 8; j++) v[j] = buf[SWZ2(lane + 32 * j) ^ xc];
        fft256p<-1>(v, lane, buf, xc, t1rr, t1iiF, t2rF, t2iF);
        __syncwarp();
#pragma unroll
        for (int j = 0; j < 8; j++)
            buf[SWZ2((lane & 7) + 8 * d0l + 32 * BRC[j]) ^ xc] = v[j];
        __syncwarp();
    }
    __syncthreads();

    // outputs: fft, u_k = fft*mask; stash u_k back in tile
    float* ur = ukreg + (size_t)b * 2 * HWSZ;
    float* ui = ur + HWSZ;
    const float* mk = maskreg + (size_t)b * HWSZ;
#pragma unroll
    for (int k = 0; k < 4; k++) {
        int row = k * 64 + rloc;
        int g = row * WW + c0 + cg * 4;
        int c = cg * 4;
        float4 m4 = *reinterpret_cast<const float4*>(mk + g);
        float mm[4] = {m4.x, m4.y, m4.z, m4.w};
        float xr[4], xi[4], kr[4], ki[4];
#pragma unroll
        for (int q = 0; q < 4; q++) {
            upk(tile[SMA(c + q, row)], xr[q], xi[q]);
            kr[q] = xr[q] * mm[q]; ki[q] = xi[q] * mm[q];
            tile[SMA(c + q, row)] = pk(kr[q], ki[q]);
        }
        *reinterpret_cast<float4*>(fr + g) = make_float4(xr[0], xr[1], xr[2], xr[3]);
        *reinterpret_cast<float4*>(fi + g) = make_float4(xi[0], xi[1], xi[2], xi[3]);
        *reinterpret_cast<float4*>(ur + g) = make_float4(kr[0], kr[1], kr[2], kr[3]);
        *reinterpret_cast<float4*>(ui + g) = make_float4(ki[0], ki[1], ki[2], ki[3]);
    }
    __syncthreads();

    // inverse FFTs (1/256 folded into t2I)
#pragma unroll 1
    for (int j2 = 0; j2 < 2; j2++) {
        int cc = wp * 2 + j2;
        u64* buf = tile + cc * CCP2;
        int xc = XC(cc);
        u64 v[8];
#pragma unroll
        for (int j = 0; j < 8; j++) v[j] = buf[SWZ2(lane + 32 * j) ^ xc];
        fft256p<1>(v, lane, buf, xc, t1rr, t1iiI, t2rI, t2iI);
        __syncwarp();
#pragma unroll
        for (int j = 0; j < 8; j++)
            buf[SWZ2((lane & 7) + 8 * d0l + 32 * BRC[j]) ^ xc] = v[j];
        __syncwarp();
    }
    __syncthreads();

    // store to staging (uifft region), float4 gmem writes
    float* dr = stage + (size_t)b * 2 * HWSZ;
    float* di = dr + HWSZ;
#pragma unroll
    for (int k = 0; k < 4; k++) {
        int row = k * 64 + rloc;
        int g = row * WW + c0 + cg * 4;
        int c = cg * 4;
        float a0, b0, a1, b1, a2, b2, a3, b3;
        upk(tile[SMA(c, row)], a0, b0);
        upk(tile[SMA(c + 1, row)], a1, b1);
        upk(tile[SMA(c + 2, row)], a2, b2);
        upk(tile[SMA(c + 3, row)], a3, b3);
        *reinterpret_cast<float4*>(dr + g) = make_float4(a0, a1, a2, a3);
        *reinterpret_cast<float4*>(di + g) = make_float4(b0, b1, b2, b3);
    }
}

// ---------- row inverse FFT (in place on uifft) + complex abs ----------
__global__ void k_row_inv(float* __restrict__ uifft, float* __restrict__ cabs) {
    __shared__ u64 scr[8 * 256];
    __shared__ u64 s_t1rr[256], s_t1ii[256];
    __shared__ float s_t2r[256], s_t2i[256];
    int t = threadIdx.x, lane = t & 31, wp = t >> 5;
    s_t1rr[t] = g_t1rr[t]; s_t1ii[t] = g_t1iiI[t];
    s_t2r[t] = g_t2rI[t];  s_t2i[t] = g_t2iI[t];
    __syncthreads();
    int row = blockIdx.x * 8 + wp, b = blockIdx.y;
    float* fr = uifft + (size_t)b * 2 * HWSZ + (size_t)row * WW;
    float* fi = fr + HWSZ;
    u64 v[8];
#pragma unroll
    for (int j = 0; j < 8; j++) v[j] = pk(fr[lane + 32 * j], fi[lane + 32 * j]);
    fft256p<1>(v, lane, scr + wp * 256, 0, s_t1rr, s_t1ii, s_t2r, s_t2i);
    int d0l = ((lane >> 4) & 1) + (((lane >> 3) & 1) << 1);
    float* ap = cabs + (size_t)b * HWSZ + (size_t)row * WW;
#pragma unroll
    for (int j = 0; j < 8; j++) {
        int n = (lane & 7) + 8 * d0l + 32 * BRC[j];
        float a, bb2; upk(v[j], a, bb2);
        fr[n] = a; fi[n] = bb2;
        ap[n] = sqrtf(a * a + bb2 * bb2);
    }
}

extern "C" void kernel_launch(void* const* d_in, const int* in_sizes, int n_in,
                              void* d_out, int out_size) {
    const float* x = (const float*)d_in[0];
    const float* w = (const float*)d_in[1];
    if (n_in >= 2 && in_sizes[0] == HWSZ) {
        x = (const float*)d_in[1];
        w = (const float*)d_in[0];
    }
    float* out   = (float*)d_out;
    float* uifft = out + OFF_UIFFT;
    float* cabs  = out + OFF_ABS;
    float* mask  = out + OFF_MASK;
    float* fft   = out + OFF_FFT;
    float* uk    = out + OFF_UK;

    unsigned sk0, sk1;
    threefry2x32(0u, 42u, 0u, 1u, sk0, sk1);

    // tile 73728 + t1 tables 6144 + t2 tables 4096 = 83968 bytes
    const int col_smem = (32 * CCP2 + 3 * 256) * 8 + 4 * 256 * 4;
    static int smem_set = 0;
    if (!smem_set) {
        cudaFuncSetAttribute(k_col, cudaFuncAttributeMaxDynamicSharedMemorySize, col_smem);
        smem_set = 1;
    }

    k_reduce<<<64, 256>>>(w);
    k_final<<<1, 256>>>();
    k_row_fwd<<<dim3(HH / 8, BB), 256>>>(x, fft, mask, sk0, sk1);
    k_col<<<dim3(WW / 32, BB), 512, col_smem>>>(fft, mask, uk, uifft);
    k_row_inv<<<dim3(HH / 8, BB), 256>>>(uifft, cabs);
}

// round 12
// speedup vs baseline: 1.3098x; 1.3098x over previous
#include <cuda_runtime.h>
#include <cstdint>
#include <math.h>

#define BB 64
#define HH 256
#define WW 256
#define HWSZ 65536
#define NTOT 4194304

#define OFF_UIFFT 0
#define OFF_ABS   8388608
#define OFF_MASK  12582912
#define OFF_FFT   16777216
#define OFF_UK    25165824

__device__ double g_partial[64];
__device__ float  g_r, g_beta;
__device__ int    g_le;
__device__ float  g_prob2[HWSZ];   // holds prob1 (pre-rescale)
__device__ float g_t1r_f[256], g_t1i_f[256], g_t1r_i[256], g_t1i_i[256];
__device__ float g_t2r_f[256], g_t2i_f[256], g_t2r_i[256], g_t2i_i[256];

// ---------------- Threefry-2x32-20 (exact jax) ----------------
__host__ __device__ __forceinline__ unsigned rotl32(unsigned v, int d) {
    return (v << d) | (v >> (32 - d));
}

__host__ __device__ __forceinline__ void threefry2x32(unsigned k0, unsigned k1,
                                                      unsigned c0, unsigned c1,
                                                      unsigned& o0, unsigned& o1) {
    unsigned ks2 = k0 ^ k1 ^ 0x1BD11BDAu;
    unsigned x0 = c0 + k0;
    unsigned x1 = c1 + k1;
#define TF_R(r) { x0 += x1; x1 = rotl32(x1, r); x1 ^= x0; }
    TF_R(13) TF_R(15) TF_R(26) TF_R(6)
    x0 += k1;  x1 += ks2 + 1u;
    TF_R(17) TF_R(29) TF_R(16) TF_R(24)
    x0 += ks2; x1 += k0 + 2u;
    TF_R(13) TF_R(15) TF_R(26) TF_R(6)
    x0 += k0;  x1 += k1 + 3u;
    TF_R(17) TF_R(29) TF_R(16) TF_R(24)
    x0 += k1;  x1 += ks2 + 4u;
    TF_R(13) TF_R(15) TF_R(26) TF_R(6)
    x0 += ks2; x1 += k0 + 5u;
#undef TF_R
    o0 = x0; o1 = x1;
}

// ---------------- XLA-exact sigmoid pieces ----------------
__device__ __forceinline__ float tanh_xla(float x) {
    float ax = fabsf(x);
    float xc = fminf(fmaxf(x, -7.90531110763549805f), 7.90531110763549805f);
    float x2 = __fmul_rn(xc, xc);
    float p = -2.76076847742355e-16f;
    p = fmaf(p, x2, 2.00018790482477e-13f);
    p = fmaf(p, x2, -8.60467152213735e-11f);
    p = fmaf(p, x2, 5.12229709037114e-08f);
    p = fmaf(p, x2, 1.48572235717979e-05f);
    p = fmaf(p, x2, 6.37261928875436e-04f);
    p = fmaf(p, x2, 4.89352455891786e-03f);
    p = __fmul_rn(p, xc);
    float q = 1.19825839466702e-06f;
    q = fmaf(q, x2, 1.18534705686654e-04f);
    q = fmaf(q, x2, 2.26843463243900e-03f);
    q = fmaf(q, x2, 4.89352518554385e-03f);
    float r = __fdiv_rn(p, q);
    return (ax < 0.0004f) ? x : r;
}

__device__ __forceinline__ float prob1_of(float wv) {
    float arg = __fmul_rn(0.5f, __fmul_rn(5.0f, wv));
    float t = tanh_xla(arg);
    return __fadd_rn(0.5f, __fmul_rn(0.5f, t));
}

// ---------------- reduction: prob1 -> g_prob2, partial sums ----------------
__global__ void k_reduce(const float* __restrict__ w) {
    __shared__ double sd[256];
    int t = threadIdx.x;
    int i0 = (blockIdx.x * 256 + t) * 4;
    float4 wq = *reinterpret_cast<const float4*>(w + i0);
    float p0 = prob1_of(wq.x), p1 = prob1_of(wq.y);
    float p2 = prob1_of(wq.z), p3 = prob1_of(wq.w);
    *reinterpret_cast<float4*>(g_prob2 + i0) = make_float4(p0, p1, p2, p3);
    sd[t] = (double)p0 + (double)p1 + (double)p2 + (double)p3;
    __syncthreads();
    for (int s = 128; s > 0; s >>= 1) {
        if (t < s) sd[t] += sd[t + s];
        __syncthreads();
    }
    if (t == 0) g_partial[blockIdx.x] = sd[0];
}

// final sum + constants + four-step twiddle tables
__global__ void k_final() {
    __shared__ double sd[64];
    int t = threadIdx.x;
    if (t < 64) sd[t] = g_partial[t];
    {
        int c = t >> 5, l = t & 31;
        float s1, c1;
        sincospif((float)(l * c) / 128.0f, &s1, &c1);
        g_t1r_f[t] = c1; g_t1i_f[t] = -s1;
        g_t1r_i[t] = c1; g_t1i_i[t] = s1;
        int d0 = ((l >> 4) & 1) + (((l >> 3) & 1) << 1);
        float s2, c2;
        sincospif((float)(c * d0) / 16.0f, &s2, &c2);
        g_t2r_f[t] = c2; g_t2i_f[t] = -s2;
        const float sc = 1.0f / 256.0f;
        g_t2r_i[t] = c2 * sc; g_t2i_i[t] = s2 * sc;
    }
    __syncthreads();
    for (int s = 32; s > 0; s >>= 1) {
        if (t < s) sd[t] += sd[t + s];
        __syncthreads();
    }
    if (t == 0) {
        float xbar = (float)(sd[0] / 65536.0);
        g_r    = __fdiv_rn(0.125f, xbar);
        g_beta = __fdiv_rn(0.875f, __fsub_rn(1.0f, xbar));
        g_le   = (g_r < 1.0f) ? 1 : 0;
    }
}

// ---------------- four-step register FFT pieces ----------------
#define SWZ(row) ((row) ^ ((row) >> 5))
#define HSQ 0.70710678118654752f

template<int SIGN>
__device__ __forceinline__ void radix8(float (&vr)[8], float (&vi)[8]) {
    const float E = (float)SIGN;
    float tr, ti;
    tr=vr[0]-vr[4]; ti=vi[0]-vi[4]; vr[0]+=vr[4]; vi[0]+=vi[4]; vr[4]=tr; vi[4]=ti;
    tr=vr[1]-vr[5]; ti=vi[1]-vi[5]; vr[1]+=vr[5]; vi[1]+=vi[5];
    vr[5]=HSQ*(tr - E*ti); vi[5]=HSQ*(ti + E*tr);
    tr=vr[2]-vr[6]; ti=vi[2]-vi[6]; vr[2]+=vr[6]; vi[2]+=vi[6];
    vr[6]=-E*ti; vi[6]=E*tr;
    tr=vr[3]-vr[7]; ti=vi[3]-vi[7]; vr[3]+=vr[7]; vi[3]+=vi[7];
    vr[7]=-HSQ*(tr + E*ti); vi[7]=HSQ*(E*tr - ti);
    tr=vr[0]-vr[2]; ti=vi[0]-vi[2]; vr[0]+=vr[2]; vi[0]+=vi[2]; vr[2]=tr; vi[2]=ti;
    tr=vr[1]-vr[3]; ti=vi[1]-vi[3]; vr[1]+=vr[3]; vi[1]+=vi[3]; vr[3]=-E*ti; vi[3]=E*tr;
    tr=vr[4]-vr[6]; ti=vi[4]-vi[6]; vr[4]+=vr[6]; vi[4]+=vi[6]; vr[6]=tr; vi[6]=ti;
    tr=vr[5]-vr[7]; ti=vi[5]-vi[7]; vr[5]+=vr[7]; vi[5]+=vi[7]; vr[7]=-E*ti; vi[7]=E*tr;
    tr=vr[0]-vr[1]; ti=vi[0]-vi[1]; vr[0]+=vr[1]; vi[0]+=vi[1]; vr[1]=tr; vi[1]=ti;
    tr=vr[2]-vr[3]; ti=vi[2]-vi[3]; vr[2]+=vr[3]; vi[2]+=vi[3]; vr[3]=tr; vi[3]=ti;
    tr=vr[4]-vr[5]; ti=vi[4]-vi[5]; vr[4]+=vr[5]; vi[4]+=vi[5]; vr[5]=tr; vi[5]=ti;
    tr=vr[6]-vr[7]; ti=vi[6]-vi[7]; vr[6]+=vr[7]; vi[6]+=vi[7]; vr[7]=tr; vi[7]=ti;
}

template<int SIGN>
__device__ __forceinline__ void radix4_lanes(float (&zr)[8], float (&zi)[8], int lane) {
    const float E = (float)SIGN;
    float s16 = (lane & 16) ? -1.0f : 1.0f;
    float s8  = (lane & 8)  ? -1.0f : 1.0f;
    bool tw = ((lane & 24) == 24);
#pragma unroll
    for (int r = 0; r < 8; r++) {
        float pr = __shfl_xor_sync(0xffffffffu, zr[r], 16);
        float pi = __shfl_xor_sync(0xffffffffu, zi[r], 16);
        float ar = fmaf(s16, zr[r], pr);
        float ai = fmaf(s16, zi[r], pi);
        if (tw) { float tt = ar; ar = -E * ai; ai = E * tt; }
        float qr = __shfl_xor_sync(0xffffffffu, ar, 8);
        float qi = __shfl_xor_sync(0xffffffffu, ai, 8);
        zr[r] = fmaf(s8, ar, qr);
        zi[r] = fmaf(s8, ai, qi);
    }
}

__device__ __constant__ int BRC[8] = {0, 4, 2, 6, 1, 5, 3, 7};

#define FFT256(SIGN, vr, vi, SADDR_R, SADDR_W, t1r, t1i, t2r, t2i)                 \
    {                                                                              \
        radix8<SIGN>(vr, vi);                                                      \
        _Pragma("unroll")                                                          \
        for (int j = 0; j < 8; j++) {                                              \
            int c = BRC[j];                                                        \
            float wr = t1r[c * 32 + lane], wi = t1i[c * 32 + lane];                \
            float nr = vr[j] * wr - vi[j] * wi;                                    \
            float ni = vr[j] * wi + vi[j] * wr;                                    \
            int row = lane + 32 * c;                                               \
            SADDR_W(row, nr, ni);                                                  \
        }                                                                          \
        __syncwarp();                                                              \
        _Pragma("unroll")                                                          \
        for (int r = 0; r < 8; r++) {                                              \
            int row = r + 8 * (lane >> 3) + 32 * (lane & 7);                       \
            SADDR_R(row, vr[r], vi[r]);                                            \
        }                                                                          \
        radix4_lanes<SIGN>(vr, vi, lane);                                          \
        _Pragma("unroll")                                                          \
        for (int r = 0; r < 8; r++) {                                              \
            float wr = t2r[r * 32 + lane], wi = t2i[r * 32 + lane];                \
            float nr = vr[r] * wr - vi[r] * wi;                                    \
            float ni = vr[r] * wi + vi[r] * wr;                                    \
            vr[r] = nr; vi[r] = ni;                                                \
        }                                                                          \
        radix8<SIGN>(vr, vi);                                                      \
    }

// ------- row forward FFT; CTAs bx>=16 also generate masks for rows 128..255 -------
__global__ void k_row_fwd(const float* __restrict__ x, float* __restrict__ fftreg,
                          float* __restrict__ maskreg, unsigned sk0, unsigned sk1) {
    __shared__ float scr[8][512];
    __shared__ float t1r[256], t1i[256], t2r[256], t2i[256];
    int t = threadIdx.x, lane = t & 31, wp = t >> 5;
    t1r[t] = g_t1r_f[t]; t1i[t] = g_t1i_f[t];
    t2r[t] = g_t2r_f[t]; t2i[t] = g_t2i_f[t];
    int bx = blockIdx.x, b = blockIdx.y;
    if (bx >= 16) {
        // mask generation for this CTA's 2048 elements (rows 128..255 half)
        float rr = g_r, bb = g_beta;
        int le = g_le;
        float* mk = maskreg + (size_t)b * HWSZ;
#pragma unroll
        for (int pass = 0; pass < 2; pass++) {
            int hw = bx * 2048 + pass * 1024 + t * 4;
            float4 p1 = *reinterpret_cast<const float4*>(g_prob2 + hw);
            float pv[4] = {p1.x, p1.y, p1.z, p1.w};
            unsigned base = (unsigned)(b * HWSZ + hw);
            float mm[4];
#pragma unroll
            for (int q = 0; q < 4; q++) {
                float p2 = le ? __fmul_rn(pv[q], rr)
                              : __fsub_rn(1.0f, __fmul_rn(__fsub_rn(1.0f, pv[q]), bb));
                unsigned o0, o1;
                threefry2x32(sk0, sk1, 0u, base + (unsigned)q, o0, o1);
                unsigned bits = o0 ^ o1;
                float u = __uint_as_float((bits >> 9) | 0x3f800000u) - 1.0f;
                mm[q] = (p2 > u) ? 1.0f : 0.0f;
            }
            *reinterpret_cast<float4*>(mk + hw) = make_float4(mm[0], mm[1], mm[2], mm[3]);
        }
    }
    __syncthreads();
    int row = bx * 8 + wp;
    const float* xp = x + (size_t)b * HWSZ + (size_t)row * WW;
    float* sc = scr[wp];
    float vr[8], vi[8];
#pragma unroll
    for (int j = 0; j < 8; j++) { vr[j] = xp[lane + 32 * j]; vi[j] = 0.0f; }
#define RW_W(rw, nr, ni) { sc[SWZ(rw)] = nr; sc[256 + SWZ(rw)] = ni; }
#define RW_R(rw, or_, oi_) { or_ = sc[SWZ(rw)]; oi_ = sc[256 + SWZ(rw)]; }
    FFT256(-1, vr, vi, RW_R, RW_W, t1r, t1i, t2r, t2i);
    int d0l = ((lane >> 4) & 1) + (((lane >> 3) & 1) << 1);
    float* fr = fftreg + (size_t)b * 2 * HWSZ + (size_t)row * WW;
    float* fi = fr + HWSZ;
#pragma unroll
    for (int j = 0; j < 8; j++) {
        int n = (lane & 7) + 8 * d0l + 32 * BRC[j];
        fr[n] = vr[j]; fi[n] = vi[j];
    }
#undef RW_W
#undef RW_R
}

// ---------- fused column kernel: 32-col tile, 512 threads ----------
// Computes masks inline for rows 0..127 (k=0,1); reads precomputed for rows 128..255.
#define CCP 288
#define SMADDR(col, row) ((col) * CCP + (SWZ(row) ^ ((((col) >> 2) & 7) << 2)))

__global__ void __launch_bounds__(512, 2)
k_col(float* __restrict__ fftreg, float* __restrict__ maskreg,
      float* __restrict__ ukreg, float* __restrict__ stage,
      unsigned sk0, unsigned sk1) {
    extern __shared__ float sm[];
    float* sre = sm;
    float* sim = sm + 32 * CCP;
    float* tw = sm + 64 * CCP;
    float* t1r_f = tw;        float* t1i_f = tw + 256;
    float* t2r_f = tw + 512;  float* t2i_f = tw + 768;
    float* t1r_i = tw + 1024; float* t1i_i = tw + 1280;
    float* t2r_i = tw + 1536; float* t2i_i = tw + 1792;
    int t = threadIdx.x, lane = t & 31, wp = t >> 5;
    int b = blockIdx.y, c0 = blockIdx.x * 32;
    int cg = t & 7, rloc = t >> 3;
    float* fr = fftreg + (size_t)b * 2 * HWSZ;
    float* fi = fr + HWSZ;

    if (t < 256) {
        t1r_f[t] = g_t1r_f[t]; t1i_f[t] = g_t1i_f[t];
        t2r_f[t] = g_t2r_f[t]; t2i_f[t] = g_t2i_f[t];
        t1r_i[t] = g_t1r_i[t]; t1i_i[t] = g_t1i_i[t];
        t2r_i[t] = g_t2r_i[t]; t2i_i[t] = g_t2i_i[t];
    }

#pragma unroll
    for (int k = 0; k < 4; k++) {
        int row = k * 64 + rloc;
        int g = row * WW + c0 + cg * 4;
        float4 vre = *reinterpret_cast<const float4*>(fr + g);
        float4 vim = *reinterpret_cast<const float4*>(fi + g);
        int c = cg * 4;
        sre[SMADDR(c, row)] = vre.x;     sim[SMADDR(c, row)] = vim.x;
        sre[SMADDR(c + 1, row)] = vre.y; sim[SMADDR(c + 1, row)] = vim.y;
        sre[SMADDR(c + 2, row)] = vre.z; sim[SMADDR(c + 2, row)] = vim.z;
        sre[SMADDR(c + 3, row)] = vre.w; sim[SMADDR(c + 3, row)] = vim.w;
    }
    __syncthreads();

#define CW_W(rw, nr, ni) { sre[SMADDR(cc, rw)] = nr; sim[SMADDR(cc, rw)] = ni; }
#define CW_R(rw, or_, oi_) { or_ = sre[SMADDR(cc, rw)]; oi_ = sim[SMADDR(cc, rw)]; }
    int d0l = ((lane >> 4) & 1) + (((lane >> 3) & 1) << 1);
#pragma unroll 1
    for (int j2 = 0; j2 < 2; j2++) {
        int cc = wp * 2 + j2;
        float vr[8], vi[8];
#pragma unroll
        for (int j = 0; j < 8; j++) {
            int row = lane + 32 * j;
            vr[j] = sre[SMADDR(cc, row)]; vi[j] = sim[SMADDR(cc, row)];
        }
        FFT256(-1, vr, vi, CW_R, CW_W, t1r_f, t1i_f, t2r_f, t2i_f);
        __syncwarp();
#pragma unroll
        for (int j = 0; j < 8; j++) {
            int row = (lane & 7) + 8 * d0l + 32 * BRC[j];
            sre[SMADDR(cc, row)] = vr[j]; sim[SMADDR(cc, row)] = vi[j];
        }
        __syncwarp();
    }
    __syncthreads();

    // outputs: fft, mask (compute rows<128 / read rows>=128), u_k; stash u_k
    float* ur = ukreg + (size_t)b * 2 * HWSZ;
    float* ui = ur + HWSZ;
    float* mk = maskreg + (size_t)b * HWSZ;
    float rr = g_r, bb2 = g_beta;
    int le = g_le;
#pragma unroll 1
    for (int k = 0; k < 4; k++) {
        int row = k * 64 + rloc;
        int g = row * WW + c0 + cg * 4;
        int c = cg * 4;
        float mm[4];
        if (k < 2) {
            float4 p1 = *reinterpret_cast<const float4*>(g_prob2 + g);
            float pv[4] = {p1.x, p1.y, p1.z, p1.w};
            unsigned base = (unsigned)(b * HWSZ + g);
#pragma unroll
            for (int q = 0; q < 4; q++) {
                float p2 = le ? __fmul_rn(pv[q], rr)
                              : __fsub_rn(1.0f, __fmul_rn(__fsub_rn(1.0f, pv[q]), bb2));
                unsigned o0, o1;
                threefry2x32(sk0, sk1, 0u, base + (unsigned)q, o0, o1);
                unsigned bits = o0 ^ o1;
                float u = __uint_as_float((bits >> 9) | 0x3f800000u) - 1.0f;
                mm[q] = (p2 > u) ? 1.0f : 0.0f;
            }
            *reinterpret_cast<float4*>(mk + g) = make_float4(mm[0], mm[1], mm[2], mm[3]);
        } else {
            float4 m4 = *reinterpret_cast<const float4*>(mk + g);
            mm[0] = m4.x; mm[1] = m4.y; mm[2] = m4.z; mm[3] = m4.w;
        }
        float xr[4], xi[4], kr[4], ki[4];
#pragma unroll
        for (int q = 0; q < 4; q++) {
            xr[q] = sre[SMADDR(c + q, row)];
            xi[q] = sim[SMADDR(c + q, row)];
            kr[q] = xr[q] * mm[q]; ki[q] = xi[q] * mm[q];
            sre[SMADDR(c + q, row)] = kr[q];
            sim[SMADDR(c + q, row)] = ki[q];
        }
        *reinterpret_cast<float4*>(fr + g) = make_float4(xr[0], xr[1], xr[2], xr[3]);
        *reinterpret_cast<float4*>(fi + g) = make_float4(xi[0], xi[1], xi[2], xi[3]);
        *reinterpret_cast<float4*>(ur + g) = make_float4(kr[0], kr[1], kr[2], kr[3]);
        *reinterpret_cast<float4*>(ui + g) = make_float4(ki[0], ki[1], ki[2], ki[3]);
    }
    __syncthreads();

#pragma unroll 1
    for (int j2 = 0; j2 < 2; j2++) {
        int cc = wp * 2 + j2;
        float vr[8], vi[8];
#pragma unroll
        for (int j = 0; j < 8; j++) {
            int row = lane + 32 * j;
            vr[j] = sre[SMADDR(cc, row)]; vi[j] = sim[SMADDR(cc, row)];
        }
        FFT256(1, vr, vi, CW_R, CW_W, t1r_i, t1i_i, t2r_i, t2i_i);
        __syncwarp();
#pragma unroll
        for (int j = 0; j < 8; j++) {
            int row = (lane & 7) + 8 * d0l + 32 * BRC[j];
            sre[SMADDR(cc, row)] = vr[j]; sim[SMADDR(cc, row)] = vi[j];
        }
        __syncwarp();
    }
    __syncthreads();
#undef CW_W
#undef CW_R

    float* dr = stage + (size_t)b * 2 * HWSZ;
    float* di = dr + HWSZ;
#pragma unroll
    for (int k = 0; k < 4; k++) {
        int row = k * 64 + rloc;
        int g = row * WW + c0 + cg * 4;
        int c = cg * 4;
        float4 vre, vim;
        vre.x = sre[SMADDR(c, row)];     vim.x = sim[SMADDR(c, row)];
        vre.y = sre[SMADDR(c + 1, row)]; vim.y = sim[SMADDR(c + 1, row)];
        vre.z = sre[SMADDR(c + 2, row)]; vim.z = sim[SMADDR(c + 2, row)];
        vre.w = sre[SMADDR(c + 3, row)]; vim.w = sim[SMADDR(c + 3, row)];
        *reinterpret_cast<float4*>(dr + g) = vre;
        *reinterpret_cast<float4*>(di + g) = vim;
    }
}

// ---------- row inverse FFT (in place on uifft) + complex abs ----------
__global__ void k_row_inv(float* __restrict__ uifft, float* __restrict__ cabs) {
    __shared__ float scr[8][512];
    __shared__ float t1r[256], t1i[256], t2r[256], t2i[256];
    int t = threadIdx.x, lane = t & 31, wp = t >> 5;
    t1r[t] = g_t1r_i[t]; t1i[t] = g_t1i_i[t];
    t2r[t] = g_t2r_i[t]; t2i[t] = g_t2i_i[t];
    __syncthreads();
    int row = blockIdx.x * 8 + wp, b = blockIdx.y;
    float* fr = uifft + (size_t)b * 2 * HWSZ + (size_t)row * WW;
    float* fi = fr + HWSZ;
    float* sc = scr[wp];
    float vr[8], vi[8];
#pragma unroll
    for (int j = 0; j < 8; j++) { vr[j] = fr[lane + 32 * j]; vi[j] = fi[lane + 32 * j]; }
#define RW_W(rw, nr, ni) { sc[SWZ(rw)] = nr; sc[256 + SWZ(rw)] = ni; }
#define RW_R(rw, or_, oi_) { or_ = sc[SWZ(rw)]; oi_ = sc[256 + SWZ(rw)]; }
    FFT256(1, vr, vi, RW_R, RW_W, t1r, t1i, t2r, t2i);
    int d0l = ((lane >> 4) & 1) + (((lane >> 3) & 1) << 1);
    float* ap = cabs + (size_t)b * HWSZ + (size_t)row * WW;
#pragma unroll
    for (int j = 0; j < 8; j++) {
        int n = (lane & 7) + 8 * d0l + 32 * BRC[j];
        fr[n] = vr[j]; fi[n] = vi[j];
        ap[n] = sqrtf(vr[j] * vr[j] + vi[j] * vi[j]);
    }
#undef RW_W
#undef RW_R
}

extern "C" void kernel_launch(void* const* d_in, const int* in_sizes, int n_in,
                              void* d_out, int out_size) {
    const float* x = (const float*)d_in[0];
    const float* w = (const float*)d_in[1];
    if (n_in >= 2 && in_sizes[0] == HWSZ) {
        x = (const float*)d_in[1];
        w = (const float*)d_in[0];
    }
    float* out   = (float*)d_out;
    float* uifft = out + OFF_UIFFT;
    float* cabs  = out + OFF_ABS;
    float* mask  = out + OFF_MASK;
    float* fft   = out + OFF_FFT;
    float* uk    = out + OFF_UK;

    unsigned sk0, sk1;
    threefry2x32(0u, 42u, 0u, 1u, sk0, sk1);

    const int col_smem = (2 * 32 * CCP + 8 * 256) * (int)sizeof(float);   // 81920
    static int smem_set = 0;
    if (!smem_set) {
        cudaFuncSetAttribute(k_col, cudaFuncAttributeMaxDynamicSharedMemorySize, col_smem);
        smem_set = 1;
    }

    k_reduce<<<64, 256>>>(w);
    k_final<<<1, 256>>>();
    k_row_fwd<<<dim3(HH / 8, BB), 256>>>(x, fft, mask, sk0, sk1);
    k_col<<<dim3(WW / 32, BB), 512, col_smem>>>(fft, mask, uk, uifft, sk0, sk1);
    k_row_inv<<<dim3(HH / 8, BB), 256>>>(uifft, cabs);
}

// round 13
// speedup vs baseline: 1.4343x; 1.0950x over previous
#include <cuda_runtime.h>
#include <cstdint>
#include <math.h>

#define BB 64
#define HH 256
#define WW 256
#define HWSZ 65536
#define NTOT 4194304

#define OFF_UIFFT 0
#define OFF_ABS   8388608
#define OFF_MASK  12582912
#define OFF_FFT   16777216
#define OFF_UK    25165824

__device__ double g_partial[64];
__device__ float  g_r, g_beta;
__device__ int    g_le;
__device__ float  g_prob2[HWSZ];   // holds prob1 (pre-rescale)
__device__ float g_t1r_f[256], g_t1i_f[256], g_t1r_i[256], g_t1i_i[256];
__device__ float g_t2r_f[256], g_t2i_f[256], g_t2r_i[256], g_t2i_i[256];

// ---------------- Threefry-2x32-20 (exact jax) ----------------
__host__ __device__ __forceinline__ unsigned rotl32(unsigned v, int d) {
    return (v << d) | (v >> (32 - d));
}

__host__ __device__ __forceinline__ void threefry2x32(unsigned k0, unsigned k1,
                                                      unsigned c0, unsigned c1,
                                                      unsigned& o0, unsigned& o1) {
    unsigned ks2 = k0 ^ k1 ^ 0x1BD11BDAu;
    unsigned x0 = c0 + k0;
    unsigned x1 = c1 + k1;
#define TF_R(r) { x0 += x1; x1 = rotl32(x1, r); x1 ^= x0; }
    TF_R(13) TF_R(15) TF_R(26) TF_R(6)
    x0 += k1;  x1 += ks2 + 1u;
    TF_R(17) TF_R(29) TF_R(16) TF_R(24)
    x0 += ks2; x1 += k0 + 2u;
    TF_R(13) TF_R(15) TF_R(26) TF_R(6)
    x0 += k0;  x1 += k1 + 3u;
    TF_R(17) TF_R(29) TF_R(16) TF_R(24)
    x0 += k1;  x1 += ks2 + 4u;
    TF_R(13) TF_R(15) TF_R(26) TF_R(6)
    x0 += ks2; x1 += k0 + 5u;
#undef TF_R
    o0 = x0; o1 = x1;
}

// ---------------- XLA-exact sigmoid pieces ----------------
__device__ __forceinline__ float tanh_xla(float x) {
    float ax = fabsf(x);
    float xc = fminf(fmaxf(x, -7.90531110763549805f), 7.90531110763549805f);
    float x2 = __fmul_rn(xc, xc);
    float p = -2.76076847742355e-16f;
    p = fmaf(p, x2, 2.00018790482477e-13f);
    p = fmaf(p, x2, -8.60467152213735e-11f);
    p = fmaf(p, x2, 5.12229709037114e-08f);
    p = fmaf(p, x2, 1.48572235717979e-05f);
    p = fmaf(p, x2, 6.37261928875436e-04f);
    p = fmaf(p, x2, 4.89352455891786e-03f);
    p = __fmul_rn(p, xc);
    float q = 1.19825839466702e-06f;
    q = fmaf(q, x2, 1.18534705686654e-04f);
    q = fmaf(q, x2, 2.26843463243900e-03f);
    q = fmaf(q, x2, 4.89352518554385e-03f);
    float r = __fdiv_rn(p, q);
    return (ax < 0.0004f) ? x : r;
}

__device__ __forceinline__ float prob1_of(float wv) {
    float arg = __fmul_rn(0.5f, __fmul_rn(5.0f, wv));
    float t = tanh_xla(arg);
    return __fadd_rn(0.5f, __fmul_rn(0.5f, t));
}

// ---------------- reduction: prob1 -> g_prob2, partial sums ----------------
__global__ void k_reduce(const float* __restrict__ w) {
    __shared__ double sd[256];
    int t = threadIdx.x;
    int i0 = (blockIdx.x * 256 + t) * 4;
    float4 wq = *reinterpret_cast<const float4*>(w + i0);
    float p0 = prob1_of(wq.x), p1 = prob1_of(wq.y);
    float p2 = prob1_of(wq.z), p3 = prob1_of(wq.w);
    *reinterpret_cast<float4*>(g_prob2 + i0) = make_float4(p0, p1, p2, p3);
    sd[t] = (double)p0 + (double)p1 + (double)p2 + (double)p3;
    __syncthreads();
    for (int s = 128; s > 0; s >>= 1) {
        if (t < s) sd[t] += sd[t + s];
        __syncthreads();
    }
    if (t == 0) g_partial[blockIdx.x] = sd[0];
}

// final sum + constants + four-step twiddle tables
__global__ void k_final() {
    __shared__ double sd[64];
    int t = threadIdx.x;
    if (t < 64) sd[t] = g_partial[t];
    {
        int c = t >> 5, l = t & 31;
        float s1, c1;
        sincospif((float)(l * c) / 128.0f, &s1, &c1);
        g_t1r_f[t] = c1; g_t1i_f[t] = -s1;
        g_t1r_i[t] = c1; g_t1i_i[t] = s1;
        int d0 = ((l >> 4) & 1) + (((l >> 3) & 1) << 1);
        float s2, c2;
        sincospif((float)(c * d0) / 16.0f, &s2, &c2);
        g_t2r_f[t] = c2; g_t2i_f[t] = -s2;
        const float sc = 1.0f / 256.0f;
        g_t2r_i[t] = c2 * sc; g_t2i_i[t] = s2 * sc;
    }
    __syncthreads();
    for (int s = 32; s > 0; s >>= 1) {
        if (t < s) sd[t] += sd[t + s];
        __syncthreads();
    }
    if (t == 0) {
        float xbar = (float)(sd[0] / 65536.0);
        g_r    = __fdiv_rn(0.125f, xbar);
        g_beta = __fdiv_rn(0.875f, __fsub_rn(1.0f, xbar));
        g_le   = (g_r < 1.0f) ? 1 : 0;
    }
}

// ---------------- four-step register FFT pieces ----------------
#define SWZ(row) ((row) ^ ((row) >> 5))
#define HSQ 0.70710678118654752f

template<int SIGN>
__device__ __forceinline__ void radix8(float (&vr)[8], float (&vi)[8]) {
    const float E = (float)SIGN;
    float tr, ti;
    tr=vr[0]-vr[4]; ti=vi[0]-vi[4]; vr[0]+=vr[4]; vi[0]+=vi[4]; vr[4]=tr; vi[4]=ti;
    tr=vr[1]-vr[5]; ti=vi[1]-vi[5]; vr[1]+=vr[5]; vi[1]+=vi[5];
    vr[5]=HSQ*(tr - E*ti); vi[5]=HSQ*(ti + E*tr);
    tr=vr[2]-vr[6]; ti=vi[2]-vi[6]; vr[2]+=vr[6]; vi[2]+=vi[6];
    vr[6]=-E*ti; vi[6]=E*tr;
    tr=vr[3]-vr[7]; ti=vi[3]-vi[7]; vr[3]+=vr[7]; vi[3]+=vi[7];
    vr[7]=-HSQ*(tr + E*ti); vi[7]=HSQ*(E*tr - ti);
    tr=vr[0]-vr[2]; ti=vi[0]-vi[2]; vr[0]+=vr[2]; vi[0]+=vi[2]; vr[2]=tr; vi[2]=ti;
    tr=vr[1]-vr[3]; ti=vi[1]-vi[3]; vr[1]+=vr[3]; vi[1]+=vi[3]; vr[3]=-E*ti; vi[3]=E*tr;
    tr=vr[4]-vr[6]; ti=vi[4]-vi[6]; vr[4]+=vr[6]; vi[4]+=vi[6]; vr[6]=tr; vi[6]=ti;
    tr=vr[5]-vr[7]; ti=vi[5]-vi[7]; vr[5]+=vr[7]; vi[5]+=vi[7]; vr[7]=-E*ti; vi[7]=E*tr;
    tr=vr[0]-vr[1]; ti=vi[0]-vi[1]; vr[0]+=vr[1]; vi[0]+=vi[1]; vr[1]=tr; vi[1]=ti;
    tr=vr[2]-vr[3]; ti=vi[2]-vi[3]; vr[2]+=vr[3]; vi[2]+=vi[3]; vr[3]=tr; vi[3]=ti;
    tr=vr[4]-vr[5]; ti=vi[4]-vi[5]; vr[4]+=vr[5]; vi[4]+=vi[5]; vr[5]=tr; vi[5]=ti;
    tr=vr[6]-vr[7]; ti=vi[6]-vi[7]; vr[6]+=vr[7]; vi[6]+=vi[7]; vr[7]=tr; vi[7]=ti;
}

template<int SIGN>
__device__ __forceinline__ void radix4_lanes(float (&zr)[8], float (&zi)[8], int lane) {
    const float E = (float)SIGN;
    float s16 = (lane & 16) ? -1.0f : 1.0f;
    float s8  = (lane & 8)  ? -1.0f : 1.0f;
    bool tw = ((lane & 24) == 24);
#pragma unroll
    for (int r = 0; r < 8; r++) {
        float pr = __shfl_xor_sync(0xffffffffu, zr[r], 16);
        float pi = __shfl_xor_sync(0xffffffffu, zi[r], 16);
        float ar = fmaf(s16, zr[r], pr);
        float ai = fmaf(s16, zi[r], pi);
        if (tw) { float tt = ar; ar = -E * ai; ai = E * tt; }
        float qr = __shfl_xor_sync(0xffffffffu, ar, 8);
        float qi = __shfl_xor_sync(0xffffffffu, ai, 8);
        zr[r] = fmaf(s8, ar, qr);
        zi[r] = fmaf(s8, ai, qi);
    }
}

__device__ __constant__ int BRC[8] = {0, 4, 2, 6, 1, 5, 3, 7};

#define FFT256(SIGN, vr, vi, SADDR_R, SADDR_W, t1r, t1i, t2r, t2i)                 \
    {                                                                              \
        radix8<SIGN>(vr, vi);                                                      \
        _Pragma("unroll")                                                          \
        for (int j = 0; j < 8; j++) {                                              \
            int c = BRC[j];                                                        \
            float wr = t1r[c * 32 + lane], wi = t1i[c * 32 + lane];                \
            float nr = vr[j] * wr - vi[j] * wi;                                    \
            float ni = vr[j] * wi + vi[j] * wr;                                    \
            int row = lane + 32 * c;                                               \
            SADDR_W(row, nr, ni);                                                  \
        }                                                                          \
        __syncwarp();                                                              \
        _Pragma("unroll")                                                          \
        for (int r = 0; r < 8; r++) {                                              \
            int row = r + 8 * (lane >> 3) + 32 * (lane & 7);                       \
            SADDR_R(row, vr[r], vi[r]);                                            \
        }                                                                          \
        radix4_lanes<SIGN>(vr, vi, lane);                                          \
        _Pragma("unroll")                                                          \
        for (int r = 0; r < 8; r++) {                                              \
            float wr = t2r[r * 32 + lane], wi = t2i[r * 32 + lane];                \
            float nr = vr[r] * wr - vi[r] * wi;                                    \
            float ni = vr[r] * wi + vi[r] * wr;                                    \
            vr[r] = nr; vi[r] = ni;                                                \
        }                                                                          \
        radix8<SIGN>(vr, vi);                                                      \
    }

// ------- row forward FFT (pure; runs concurrent with reduce/final) -------
__global__ void k_row_fwd(const float* __restrict__ x, float* __restrict__ fftreg) {
    __shared__ float scr[8][512];
    __shared__ float t1r[256], t1i[256], t2r[256], t2i[256];
    int t = threadIdx.x, lane = t & 31, wp = t >> 5;
    t1r[t] = g_t1r_f[t]; t1i[t] = g_t1i_f[t];
    t2r[t] = g_t2r_f[t]; t2i[t] = g_t2i_f[t];
    __syncthreads();
    int row = blockIdx.x * 8 + wp, b = blockIdx.y;
    const float* xp = x + (size_t)b * HWSZ + (size_t)row * WW;
    float* sc = scr[wp];
    float vr[8], vi[8];
#pragma unroll
    for (int j = 0; j < 8; j++) { vr[j] = xp[lane + 32 * j]; vi[j] = 0.0f; }
#define RW_W(rw, nr, ni) { sc[SWZ(rw)] = nr; sc[256 + SWZ(rw)] = ni; }
#define RW_R(rw, or_, oi_) { or_ = sc[SWZ(rw)]; oi_ = sc[256 + SWZ(rw)]; }
    FFT256(-1, vr, vi, RW_R, RW_W, t1r, t1i, t2r, t2i);
    int d0l = ((lane >> 4) & 1) + (((lane >> 3) & 1) << 1);
    float* fr = fftreg + (size_t)b * 2 * HWSZ + (size_t)row * WW;
    float* fi = fr + HWSZ;
#pragma unroll
    for (int j = 0; j < 8; j++) {
        int n = (lane & 7) + 8 * d0l + 32 * BRC[j];
        fr[n] = vr[j]; fi[n] = vi[j];
    }
#undef RW_W
#undef RW_R
}

// ---------- fused column kernel: 16-col tile, 256 threads, 4 CTAs/SM ----------
// per-column XOR in bits 3..4 (verified conflict-free for all phases at 16 cols)
#define CCP 288
#define SMADDR(col, row) ((col) * CCP + (SWZ(row) ^ ((((col) >> 2) & 3) << 3)))

__global__ void __launch_bounds__(256, 4)
k_col(float* __restrict__ fftreg, float* __restrict__ maskreg,
      float* __restrict__ ukreg, float* __restrict__ stage,
      unsigned sk0, unsigned sk1) {
    extern __shared__ float sm[];
    float* sre = sm;
    float* sim = sm + 16 * CCP;
    float* tw = sm + 32 * CCP;
    float* t1r_f = tw;        float* t1i_f = tw + 256;
    float* t2r_f = tw + 512;  float* t2i_f = tw + 768;
    float* t1r_i = tw + 1024; float* t1i_i = tw + 1280;
    float* t2r_i = tw + 1536; float* t2i_i = tw + 1792;
    int t = threadIdx.x, lane = t & 31, wp = t >> 5;   // wp 0..7
    int b = blockIdx.y, c0 = blockIdx.x * 16;
    int cg = t & 3, rloc = t >> 2;                     // rloc 0..63
    float* fr = fftreg + (size_t)b * 2 * HWSZ;
    float* fi = fr + HWSZ;

    t1r_f[t] = g_t1r_f[t]; t1i_f[t] = g_t1i_f[t];
    t2r_f[t] = g_t2r_f[t]; t2i_f[t] = g_t2i_f[t];
    t1r_i[t] = g_t1r_i[t]; t1i_i[t] = g_t1i_i[t];
    t2r_i[t] = g_t2r_i[t]; t2i_i[t] = g_t2i_i[t];

    // load 256x16 tile (float4 gmem, scalar swizzled smem)
#pragma unroll
    for (int k = 0; k < 4; k++) {
        int row = k * 64 + rloc;
        int g = row * WW + c0 + cg * 4;
        float4 vre = *reinterpret_cast<const float4*>(fr + g);
        float4 vim = *reinterpret_cast<const float4*>(fi + g);
        int c = cg * 4;
        sre[SMADDR(c, row)] = vre.x;     sim[SMADDR(c, row)] = vim.x;
        sre[SMADDR(c + 1, row)] = vre.y; sim[SMADDR(c + 1, row)] = vim.y;
        sre[SMADDR(c + 2, row)] = vre.z; sim[SMADDR(c + 2, row)] = vim.z;
        sre[SMADDR(c + 3, row)] = vre.w; sim[SMADDR(c + 3, row)] = vim.w;
    }
    __syncthreads();

#define CW_W(rw, nr, ni) { sre[SMADDR(cc, rw)] = nr; sim[SMADDR(cc, rw)] = ni; }
#define CW_R(rw, or_, oi_) { or_ = sre[SMADDR(cc, rw)]; oi_ = sim[SMADDR(cc, rw)]; }
    int d0l = ((lane >> 4) & 1) + (((lane >> 3) & 1) << 1);
    // forward FFTs: 2 columns per warp
#pragma unroll 1
    for (int j2 = 0; j2 < 2; j2++) {
        int cc = wp * 2 + j2;
        float vr[8], vi[8];
#pragma unroll
        for (int j = 0; j < 8; j++) {
            int row = lane + 32 * j;
            vr[j] = sre[SMADDR(cc, row)]; vi[j] = sim[SMADDR(cc, row)];
        }
        FFT256(-1, vr, vi, CW_R, CW_W, t1r_f, t1i_f, t2r_f, t2i_f);
        __syncwarp();
#pragma unroll
        for (int j = 0; j < 8; j++) {
            int row = (lane & 7) + 8 * d0l + 32 * BRC[j];
            sre[SMADDR(cc, row)] = vr[j]; sim[SMADDR(cc, row)] = vi[j];
        }
        __syncwarp();
    }
    __syncthreads();

    // outputs: fft, mask (threefry, all of it), u_k; stash u_k in smem
    float* ur = ukreg + (size_t)b * 2 * HWSZ;
    float* ui = ur + HWSZ;
    float* mk = maskreg + (size_t)b * HWSZ;
    float rr = g_r, bb2 = g_beta;
    int le = g_le;
#pragma unroll 1
    for (int k = 0; k < 4; k++) {
        int row = k * 64 + rloc;
        int g = row * WW + c0 + cg * 4;
        int c = cg * 4;
        float mm[4];
        float4 p1 = *reinterpret_cast<const float4*>(g_prob2 + g);
        float pv[4] = {p1.x, p1.y, p1.z, p1.w};
        unsigned base = (unsigned)(b * HWSZ + g);
#pragma unroll
        for (int q = 0; q < 4; q++) {
            float p2 = le ? __fmul_rn(pv[q], rr)
                          : __fsub_rn(1.0f, __fmul_rn(__fsub_rn(1.0f, pv[q]), bb2));
            unsigned o0, o1;
            threefry2x32(sk0, sk1, 0u, base + (unsigned)q, o0, o1);
            unsigned bits = o0 ^ o1;
            float u = __uint_as_float((bits >> 9) | 0x3f800000u) - 1.0f;
            mm[q] = (p2 > u) ? 1.0f : 0.0f;
        }
        *reinterpret_cast<float4*>(mk + g) = make_float4(mm[0], mm[1], mm[2], mm[3]);
        float xr[4], xi[4], kr[4], ki[4];
#pragma unroll
        for (int q = 0; q < 4; q++) {
            xr[q] = sre[SMADDR(c + q, row)];
            xi[q] = sim[SMADDR(c + q, row)];
            kr[q] = xr[q] * mm[q]; ki[q] = xi[q] * mm[q];
            sre[SMADDR(c + q, row)] = kr[q];
            sim[SMADDR(c + q, row)] = ki[q];
        }
        *reinterpret_cast<float4*>(fr + g) = make_float4(xr[0], xr[1], xr[2], xr[3]);
        *reinterpret_cast<float4*>(fi + g) = make_float4(xi[0], xi[1], xi[2], xi[3]);
        *reinterpret_cast<float4*>(ur + g) = make_float4(kr[0], kr[1], kr[2], kr[3]);
        *reinterpret_cast<float4*>(ui + g) = make_float4(ki[0], ki[1], ki[2], ki[3]);
    }
    __syncthreads();

    // inverse FFTs (1/256 folded into t2_i)
#pragma unroll 1
    for (int j2 = 0; j2 < 2; j2++) {
        int cc = wp * 2 + j2;
        float vr[8], vi[8];
#pragma unroll
        for (int j = 0; j < 8; j++) {
            int row = lane + 32 * j;
            vr[j] = sre[SMADDR(cc, row)]; vi[j] = sim[SMADDR(cc, row)];
        }
        FFT256(1, vr, vi, CW_R, CW_W, t1r_i, t1i_i, t2r_i, t2i_i);
        __syncwarp();
#pragma unroll
        for (int j = 0; j < 8; j++) {
            int row = (lane & 7) + 8 * d0l + 32 * BRC[j];
            sre[SMADDR(cc, row)] = vr[j]; sim[SMADDR(cc, row)] = vi[j];
        }
        __syncwarp();
    }
    __syncthreads();
#undef CW_W
#undef CW_R

    // store to staging (uifft region)
    float* dr = stage + (size_t)b * 2 * HWSZ;
    float* di = dr + HWSZ;
#pragma unroll
    for (int k = 0; k < 4; k++) {
        int row = k * 64 + rloc;
        int g = row * WW + c0 + cg * 4;
        int c = cg * 4;
        float4 vre, vim;
        vre.x = sre[SMADDR(c, row)];     vim.x = sim[SMADDR(c, row)];
        vre.y = sre[SMADDR(c + 1, row)]; vim.y = sim[SMADDR(c + 1, row)];
        vre.z = sre[SMADDR(c + 2, row)]; vim.z = sim[SMADDR(c + 2, row)];
        vre.w = sre[SMADDR(c + 3, row)]; vim.w = sim[SMADDR(c + 3, row)];
        *reinterpret_cast<float4*>(dr + g) = vre;
        *reinterpret_cast<float4*>(di + g) = vim;
    }
}

// ---------- row inverse FFT (in place on uifft) + complex abs ----------
__global__ void k_row_inv(float* __restrict__ uifft, float* __restrict__ cabs) {
    __shared__ float scr[8][512];
    __shared__ float t1r[256], t1i[256], t2r[256], t2i[256];
    int t = threadIdx.x, lane = t & 31, wp = t >> 5;
    t1r[t] = g_t1r_i[t]; t1i[t] = g_t1i_i[t];
    t2r[t] = g_t2r_i[t]; t2i[t] = g_t2i_i[t];
    __syncthreads();
    int row = blockIdx.x * 8 + wp, b = blockIdx.y;
    float* fr = uifft + (size_t)b * 2 * HWSZ + (size_t)row * WW;
    float* fi = fr + HWSZ;
    float* sc = scr[wp];
    float vr[8], vi[8];
#pragma unroll
    for (int j = 0; j < 8; j++) { vr[j] = fr[lane + 32 * j]; vi[j] = fi[lane + 32 * j]; }
#define RW_W(rw, nr, ni) { sc[SWZ(rw)] = nr; sc[256 + SWZ(rw)] = ni; }
#define RW_R(rw, or_, oi_) { or_ = sc[SWZ(rw)]; oi_ = sc[256 + SWZ(rw)]; }
    FFT256(1, vr, vi, RW_R, RW_W, t1r, t1i, t2r, t2i);
    int d0l = ((lane >> 4) & 1) + (((lane >> 3) & 1) << 1);
    float* ap = cabs + (size_t)b * HWSZ + (size_t)row * WW;
#pragma unroll
    for (int j = 0; j < 8; j++) {
        int n = (lane & 7) + 8 * d0l + 32 * BRC[j];
        fr[n] = vr[j]; fi[n] = vi[j];
        ap[n] = sqrtf(vr[j] * vr[j] + vi[j] * vi[j]);
    }
#undef RW_W
#undef RW_R
}

extern "C" void kernel_launch(void* const* d_in, const int* in_sizes, int n_in,
                              void* d_out, int out_size) {
    const float* x = (const float*)d_in[0];
    const float* w = (const float*)d_in[1];
    if (n_in >= 2 && in_sizes[0] == HWSZ) {
        x = (const float*)d_in[1];
        w = (const float*)d_in[0];
    }
    float* out   = (float*)d_out;
    float* uifft = out + OFF_UIFFT;
    float* cabs  = out + OFF_ABS;
    float* mask  = out + OFF_MASK;
    float* fft   = out + OFF_FFT;
    float* uk    = out + OFF_UK;

    unsigned sk0, sk1;
    threefry2x32(0u, 42u, 0u, 1u, sk0, sk1);

    const int col_smem = (2 * 16 * CCP + 8 * 256) * (int)sizeof(float);   // 45056

    static cudaStream_t s1 = 0;
    static cudaEvent_t ev_fork = 0, ev_join = 0;
    static int inited = 0;
    if (!inited) {
        cudaStreamCreateWithFlags(&s1, cudaStreamNonBlocking);
        cudaEventCreateWithFlags(&ev_fork, cudaEventDisableTiming);
        cudaEventCreateWithFlags(&ev_join, cudaEventDisableTiming);
        cudaFuncSetAttribute(k_col, cudaFuncAttributeMaxDynamicSharedMemorySize, col_smem);
        inited = 1;
    }

    // fork: reduce+final on s1, row_fwd on main stream (independent)
    cudaEventRecord(ev_fork, 0);
    cudaStreamWaitEvent(s1, ev_fork, 0);
    k_reduce<<<64, 256, 0, s1>>>(w);
    k_final<<<1, 256, 0, s1>>>();
    cudaEventRecord(ev_join, s1);

    k_row_fwd<<<dim3(HH / 8, BB), 256>>>(x, fft);

    // join: k_col needs both row_fwd (main) and final (s1)
    cudaStreamWaitEvent(0, ev_join, 0);
    k_col<<<dim3(WW / 16, BB), 256, col_smem>>>(fft, mask, uk, uifft, sk0, sk1);
    k_row_inv<<<dim3(HH / 8, BB), 256>>>(uifft, cabs);
}

// round 14
// speedup vs baseline: 1.4937x; 1.0415x over previous
#include <cuda_runtime.h>
#include <cstdint>
#include <math.h>

#define BB 64
#define HH 256
#define WW 256
#define HWSZ 65536
#define NTOT 4194304

#define OFF_UIFFT 0
#define OFF_ABS   8388608
#define OFF_MASK  12582912
#define OFF_FFT   16777216
#define OFF_UK    25165824

__device__ double g_partial[64];
__device__ float  g_r, g_beta;
__device__ int    g_le;
__device__ float  g_prob2[HWSZ];   // holds prob1 (pre-rescale)
__device__ float g_t1r_f[256], g_t1i_f[256], g_t1r_i[256], g_t1i_i[256];
__device__ float g_t2r_f[256], g_t2i_f[256], g_t2r_i[256], g_t2i_i[256];

// ---------------- Threefry-2x32-20 (exact jax) ----------------
__host__ __device__ __forceinline__ unsigned rotl32(unsigned v, int d) {
    return (v << d) | (v >> (32 - d));
}

__host__ __device__ __forceinline__ void threefry2x32(unsigned k0, unsigned k1,
                                                      unsigned c0, unsigned c1,
                                                      unsigned& o0, unsigned& o1) {
    unsigned ks2 = k0 ^ k1 ^ 0x1BD11BDAu;
    unsigned x0 = c0 + k0;
    unsigned x1 = c1 + k1;
#define TF_R(r) { x0 += x1; x1 = rotl32(x1, r); x1 ^= x0; }
    TF_R(13) TF_R(15) TF_R(26) TF_R(6)
    x0 += k1;  x1 += ks2 + 1u;
    TF_R(17) TF_R(29) TF_R(16) TF_R(24)
    x0 += ks2; x1 += k0 + 2u;
    TF_R(13) TF_R(15) TF_R(26) TF_R(6)
    x0 += k0;  x1 += k1 + 3u;
    TF_R(17) TF_R(29) TF_R(16) TF_R(24)
    x0 += k1;  x1 += ks2 + 4u;
    TF_R(13) TF_R(15) TF_R(26) TF_R(6)
    x0 += ks2; x1 += k0 + 5u;
#undef TF_R
    o0 = x0; o1 = x1;
}

// ---------------- XLA-exact sigmoid pieces ----------------
__device__ __forceinline__ float tanh_xla(float x) {
    float ax = fabsf(x);
    float xc = fminf(fmaxf(x, -7.90531110763549805f), 7.90531110763549805f);
    float x2 = __fmul_rn(xc, xc);
    float p = -2.76076847742355e-16f;
    p = fmaf(p, x2, 2.00018790482477e-13f);
    p = fmaf(p, x2, -8.60467152213735e-11f);
    p = fmaf(p, x2, 5.12229709037114e-08f);
    p = fmaf(p, x2, 1.48572235717979e-05f);
    p = fmaf(p, x2, 6.37261928875436e-04f);
    p = fmaf(p, x2, 4.89352455891786e-03f);
    p = __fmul_rn(p, xc);
    float q = 1.19825839466702e-06f;
    q = fmaf(q, x2, 1.18534705686654e-04f);
    q = fmaf(q, x2, 2.26843463243900e-03f);
    q = fmaf(q, x2, 4.89352518554385e-03f);
    float r = __fdiv_rn(p, q);
    return (ax < 0.0004f) ? x : r;
}

__device__ __forceinline__ float prob1_of(float wv) {
    float arg = __fmul_rn(0.5f, __fmul_rn(5.0f, wv));
    float t = tanh_xla(arg);
    return __fadd_rn(0.5f, __fmul_rn(0.5f, t));
}

// ---------------- reduction: prob1 -> g_prob2, partial sums ----------------
__global__ void k_reduce(const float* __restrict__ w) {
    __shared__ double sd[256];
    int t = threadIdx.x;
    int i0 = (blockIdx.x * 256 + t) * 4;
    float4 wq = *reinterpret_cast<const float4*>(w + i0);
    float p0 = prob1_of(wq.x), p1 = prob1_of(wq.y);
    float p2 = prob1_of(wq.z), p3 = prob1_of(wq.w);
    *reinterpret_cast<float4*>(g_prob2 + i0) = make_float4(p0, p1, p2, p3);
    sd[t] = (double)p0 + (double)p1 + (double)p2 + (double)p3;
    __syncthreads();
    for (int s = 128; s > 0; s >>= 1) {
        if (t < s) sd[t] += sd[t + s];
        __syncthreads();
    }
    if (t == 0) g_partial[blockIdx.x] = sd[0];
}

// final sum + constants + four-step twiddle tables
__global__ void k_final() {
    __shared__ double sd[64];
    int t = threadIdx.x;
    if (t < 64) sd[t] = g_partial[t];
    {
        int c = t >> 5, l = t & 31;
        float s1, c1;
        sincospif((float)(l * c) / 128.0f, &s1, &c1);
        g_t1r_f[t] = c1; g_t1i_f[t] = -s1;
        g_t1r_i[t] = c1; g_t1i_i[t] = s1;
        int d0 = ((l >> 4) & 1) + (((l >> 3) & 1) << 1);
        float s2, c2;
        sincospif((float)(c * d0) / 16.0f, &s2, &c2);
        g_t2r_f[t] = c2; g_t2i_f[t] = -s2;
        const float sc = 1.0f / 256.0f;
        g_t2r_i[t] = c2 * sc; g_t2i_i[t] = s2 * sc;
    }
    __syncthreads();
    for (int s = 32; s > 0; s >>= 1) {
        if (t < s) sd[t] += sd[t + s];
        __syncthreads();
    }
    if (t == 0) {
        float xbar = (float)(sd[0] / 65536.0);
        g_r    = __fdiv_rn(0.125f, xbar);
        g_beta = __fdiv_rn(0.875f, __fsub_rn(1.0f, xbar));
        g_le   = (g_r < 1.0f) ? 1 : 0;
    }
}

// ---------------- four-step register FFT pieces ----------------
#define SWZ(row) ((row) ^ ((row) >> 5))
#define HSQ 0.70710678118654752f

template<int SIGN>
__device__ __forceinline__ void radix8(float (&vr)[8], float (&vi)[8]) {
    const float E = (float)SIGN;
    float tr, ti;
    tr=vr[0]-vr[4]; ti=vi[0]-vi[4]; vr[0]+=vr[4]; vi[0]+=vi[4]; vr[4]=tr; vi[4]=ti;
    tr=vr[1]-vr[5]; ti=vi[1]-vi[5]; vr[1]+=vr[5]; vi[1]+=vi[5];
    vr[5]=HSQ*(tr - E*ti); vi[5]=HSQ*(ti + E*tr);
    tr=vr[2]-vr[6]; ti=vi[2]-vi[6]; vr[2]+=vr[6]; vi[2]+=vi[6];
    vr[6]=-E*ti; vi[6]=E*tr;
    tr=vr[3]-vr[7]; ti=vi[3]-vi[7]; vr[3]+=vr[7]; vi[3]+=vi[7];
    vr[7]=-HSQ*(tr + E*ti); vi[7]=HSQ*(E*tr - ti);
    tr=vr[0]-vr[2]; ti=vi[0]-vi[2]; vr[0]+=vr[2]; vi[0]+=vi[2]; vr[2]=tr; vi[2]=ti;
    tr=vr[1]-vr[3]; ti=vi[1]-vi[3]; vr[1]+=vr[3]; vi[1]+=vi[3]; vr[3]=-E*ti; vi[3]=E*tr;
    tr=vr[4]-vr[6]; ti=vi[4]-vi[6]; vr[4]+=vr[6]; vi[4]+=vi[6]; vr[6]=tr; vi[6]=ti;
    tr=vr[5]-vr[7]; ti=vi[5]-vi[7]; vr[5]+=vr[7]; vi[5]+=vi[7]; vr[7]=-E*ti; vi[7]=E*tr;
    tr=vr[0]-vr[1]; ti=vi[0]-vi[1]; vr[0]+=vr[1]; vi[0]+=vi[1]; vr[1]=tr; vi[1]=ti;
    tr=vr[2]-vr[3]; ti=vi[2]-vi[3]; vr[2]+=vr[3]; vi[2]+=vi[3]; vr[3]=tr; vi[3]=ti;
    tr=vr[4]-vr[5]; ti=vi[4]-vi[5]; vr[4]+=vr[5]; vi[4]+=vi[5]; vr[5]=tr; vi[5]=ti;
    tr=vr[6]-vr[7]; ti=vi[6]-vi[7]; vr[6]+=vr[7]; vi[6]+=vi[7]; vr[7]=tr; vi[7]=ti;
}

template<int SIGN>
__device__ __forceinline__ void radix4_lanes(float (&zr)[8], float (&zi)[8], int lane) {
    const float E = (float)SIGN;
    float s16 = (lane & 16) ? -1.0f : 1.0f;
    float s8  = (lane & 8)  ? -1.0f : 1.0f;
    bool tw = ((lane & 24) == 24);
#pragma unroll
    for (int r = 0; r < 8; r++) {
        float pr = __shfl_xor_sync(0xffffffffu, zr[r], 16);
        float pi = __shfl_xor_sync(0xffffffffu, zi[r], 16);
        float ar = fmaf(s16, zr[r], pr);
        float ai = fmaf(s16, zi[r], pi);
        if (tw) { float tt = ar; ar = -E * ai; ai = E * tt; }
        float qr = __shfl_xor_sync(0xffffffffu, ar, 8);
        float qi = __shfl_xor_sync(0xffffffffu, ar == ar ? ai : ai, 8);
        qi = __shfl_xor_sync(0xffffffffu, ai, 8);
        zr[r] = fmaf(s8, ar, qr);
        zi[r] = fmaf(s8, ai, qi);
    }
}

__device__ __constant__ int BRC[8] = {0, 4, 2, 6, 1, 5, 3, 7};

// NEGI=1: tables hold FORWARD twiddles but we need conjugate (inverse) — the
// -wi folds into FFMA negation modifiers (zero extra instructions).
#define FFT256(SIGN, NEGI, vr, vi, SADDR_R, SADDR_W, t1r, t1i, t2r, t2i)           \
    {                                                                              \
        radix8<SIGN>(vr, vi);                                                      \
        _Pragma("unroll")                                                          \
        for (int j = 0; j < 8; j++) {                                              \
            int c = BRC[j];                                                        \
            float wr = t1r[c * 32 + lane];                                         \
            float wi = (NEGI) ? -t1i[c * 32 + lane] : t1i[c * 32 + lane];          \
            float nr = vr[j] * wr - vi[j] * wi;                                    \
            float ni = vr[j] * wi + vi[j] * wr;                                    \
            int row = lane + 32 * c;                                               \
            SADDR_W(row, nr, ni);                                                  \
        }                                                                          \
        __syncwarp();                                                              \
        _Pragma("unroll")                                                          \
        for (int r = 0; r < 8; r++) {                                              \
            int row = r + 8 * (lane >> 3) + 32 * (lane & 7);                       \
            SADDR_R(row, vr[r], vi[r]);                                            \
        }                                                                          \
        radix4_lanes<SIGN>(vr, vi, lane);                                          \
        _Pragma("unroll")                                                          \
        for (int r = 0; r < 8; r++) {                                              \
            float wr = t2r[r * 32 + lane];                                         \
            float wi = (NEGI) ? -t2i[r * 32 + lane] : t2i[r * 32 + lane];          \
            float nr = vr[r] * wr - vi[r] * wi;                                    \
            float ni = vr[r] * wi + vi[r] * wr;                                    \
            vr[r] = nr; vi[r] = ni;                                                \
        }                                                                          \
        radix8<SIGN>(vr, vi);                                                      \
    }

// ------- row forward FFT (pure; batch offset for stream split) -------
__global__ void k_row_fwd(const float* __restrict__ x, float* __restrict__ fftreg,
                          int bofs) {
    __shared__ float scr[8][512];
    __shared__ float t1r[256], t1i[256], t2r[256], t2i[256];
    int t = threadIdx.x, lane = t & 31, wp = t >> 5;
    t1r[t] = g_t1r_f[t]; t1i[t] = g_t1i_f[t];
    t2r[t] = g_t2r_f[t]; t2i[t] = g_t2i_f[t];
    __syncthreads();
    int row = blockIdx.x * 8 + wp, b = blockIdx.y + bofs;
    const float* xp = x + (size_t)b * HWSZ + (size_t)row * WW;
    float* sc = scr[wp];
    float vr[8], vi[8];
#pragma unroll
    for (int j = 0; j < 8; j++) { vr[j] = xp[lane + 32 * j]; vi[j] = 0.0f; }
#define RW_W(rw, nr, ni) { sc[SWZ(rw)] = nr; sc[256 + SWZ(rw)] = ni; }
#define RW_R(rw, or_, oi_) { or_ = sc[SWZ(rw)]; oi_ = sc[256 + SWZ(rw)]; }
    FFT256(-1, 0, vr, vi, RW_R, RW_W, t1r, t1i, t2r, t2i);
    int d0l = ((lane >> 4) & 1) + (((lane >> 3) & 1) << 1);
    float* fr = fftreg + (size_t)b * 2 * HWSZ + (size_t)row * WW;
    float* fi = fr + HWSZ;
#pragma unroll
    for (int j = 0; j < 8; j++) {
        int n = (lane & 7) + 8 * d0l + 32 * BRC[j];
        fr[n] = vr[j]; fi[n] = vi[j];
    }
#undef RW_W
#undef RW_R
}

// ---------- fused column kernel: 16-col tile, 256 threads, fwd tables only ----------
#define CCP 256
#define SMADDR(col, row) ((col) * CCP + (SWZ(row) ^ ((((col) >> 2) & 3) << 3)))

__global__ void __launch_bounds__(256, 3)
k_col(float* __restrict__ fftreg, float* __restrict__ maskreg,
      float* __restrict__ ukreg, float* __restrict__ stage,
      unsigned sk0, unsigned sk1, int bofs) {
    extern __shared__ float sm[];
    float* sre = sm;
    float* sim = sm + 16 * CCP;
    float* tw = sm + 32 * CCP;
    float* t1r_f = tw;        float* t1i_f = tw + 256;
    float* t2r_f = tw + 512;  float* t2i_f = tw + 768;
    int t = threadIdx.x, lane = t & 31, wp = t >> 5;
    int b = blockIdx.y + bofs, c0 = blockIdx.x * 16;
    int cg = t & 3, rloc = t >> 2;
    float* fr = fftreg + (size_t)b * 2 * HWSZ;
    float* fi = fr + HWSZ;

    t1r_f[t] = g_t1r_f[t]; t1i_f[t] = g_t1i_f[t];
    t2r_f[t] = g_t2r_f[t]; t2i_f[t] = g_t2i_f[t];

#pragma unroll
    for (int k = 0; k < 4; k++) {
        int row = k * 64 + rloc;
        int g = row * WW + c0 + cg * 4;
        float4 vre = *reinterpret_cast<const float4*>(fr + g);
        float4 vim = *reinterpret_cast<const float4*>(fi + g);
        int c = cg * 4;
        sre[SMADDR(c, row)] = vre.x;     sim[SMADDR(c, row)] = vim.x;
        sre[SMADDR(c + 1, row)] = vre.y; sim[SMADDR(c + 1, row)] = vim.y;
        sre[SMADDR(c + 2, row)] = vre.z; sim[SMADDR(c + 2, row)] = vim.z;
        sre[SMADDR(c + 3, row)] = vre.w; sim[SMADDR(c + 3, row)] = vim.w;
    }
    __syncthreads();

#define CW_W(rw, nr, ni) { sre[SMADDR(cc, rw)] = nr; sim[SMADDR(cc, rw)] = ni; }
#define CW_R(rw, or_, oi_) { or_ = sre[SMADDR(cc, rw)]; oi_ = sim[SMADDR(cc, rw)]; }
    int d0l = ((lane >> 4) & 1) + (((lane >> 3) & 1) << 1);
#pragma unroll 1
    for (int j2 = 0; j2 < 2; j2++) {
        int cc = wp * 2 + j2;
        float vr[8], vi[8];
#pragma unroll
        for (int j = 0; j < 8; j++) {
            int row = lane + 32 * j;
            vr[j] = sre[SMADDR(cc, row)]; vi[j] = sim[SMADDR(cc, row)];
        }
        FFT256(-1, 0, vr, vi, CW_R, CW_W, t1r_f, t1i_f, t2r_f, t2i_f);
        __syncwarp();
#pragma unroll
        for (int j = 0; j < 8; j++) {
            int row = (lane & 7) + 8 * d0l + 32 * BRC[j];
            sre[SMADDR(cc, row)] = vr[j]; sim[SMADDR(cc, row)] = vi[j];
        }
        __syncwarp();
    }
    __syncthreads();

    // outputs: fft, mask (threefry), u_k; stash u_k in smem
    float* ur = ukreg + (size_t)b * 2 * HWSZ;
    float* ui = ur + HWSZ;
    float* mk = maskreg + (size_t)b * HWSZ;
    float rr = g_r, bb2 = g_beta;
    int le = g_le;
#pragma unroll 1
    for (int k = 0; k < 4; k++) {
        int row = k * 64 + rloc;
        int g = row * WW + c0 + cg * 4;
        int c = cg * 4;
        float mm[4];
        float4 p1 = *reinterpret_cast<const float4*>(g_prob2 + g);
        float pv[4] = {p1.x, p1.y, p1.z, p1.w};
        unsigned base = (unsigned)(b * HWSZ + g);
#pragma unroll
        for (int q = 0; q < 4; q++) {
            float p2 = le ? __fmul_rn(pv[q], rr)
                          : __fsub_rn(1.0f, __fmul_rn(__fsub_rn(1.0f, pv[q]), bb2));
            unsigned o0, o1;
            threefry2x32(sk0, sk1, 0u, base + (unsigned)q, o0, o1);
            unsigned bits = o0 ^ o1;
            float u = __uint_as_float((bits >> 9) | 0x3f800000u) - 1.0f;
            mm[q] = (p2 > u) ? 1.0f : 0.0f;
        }
        *reinterpret_cast<float4*>(mk + g) = make_float4(mm[0], mm[1], mm[2], mm[3]);
        float xr[4], xi[4], kr[4], ki[4];
#pragma unroll
        for (int q = 0; q < 4; q++) {
            xr[q] = sre[SMADDR(c + q, row)];
            xi[q] = sim[SMADDR(c + q, row)];
            kr[q] = xr[q] * mm[q]; ki[q] = xi[q] * mm[q];
            sre[SMADDR(c + q, row)] = kr[q];
            sim[SMADDR(c + q, row)] = ki[q];
        }
        *reinterpret_cast<float4*>(fr + g) = make_float4(xr[0], xr[1], xr[2], xr[3]);
        *reinterpret_cast<float4*>(fi + g) = make_float4(xi[0], xi[1], xi[2], xi[3]);
        *reinterpret_cast<float4*>(ur + g) = make_float4(kr[0], kr[1], kr[2], kr[3]);
        *reinterpret_cast<float4*>(ui + g) = make_float4(ki[0], ki[1], ki[2], ki[3]);
    }
    __syncthreads();

    // inverse FFTs: forward tables with conjugated twiddles; explicit 1/256
#pragma unroll 1
    for (int j2 = 0; j2 < 2; j2++) {
        int cc = wp * 2 + j2;
        float vr[8], vi[8];
#pragma unroll
        for (int j = 0; j < 8; j++) {
            int row = lane + 32 * j;
            vr[j] = sre[SMADDR(cc, row)]; vi[j] = sim[SMADDR(cc, row)];
        }
        FFT256(1, 1, vr, vi, CW_R, CW_W, t1r_f, t1i_f, t2r_f, t2i_f);
        __syncwarp();
        const float sc = 1.0f / 256.0f;
#pragma unroll
        for (int j = 0; j < 8; j++) {
            int row = (lane & 7) + 8 * d0l + 32 * BRC[j];
            sre[SMADDR(cc, row)] = vr[j] * sc; sim[SMADDR(cc, row)] = vi[j] * sc;
        }
        __syncwarp();
    }
    __syncthreads();
#undef CW_W
#undef CW_R

    float* dr = stage + (size_t)b * 2 * HWSZ;
    float* di = dr + HWSZ;
#pragma unroll
    for (int k = 0; k < 4; k++) {
        int row = k * 64 + rloc;
        int g = row * WW + c0 + cg * 4;
        int c = cg * 4;
        float4 vre, vim;
        vre.x = sre[SMADDR(c, row)];     vim.x = sim[SMADDR(c, row)];
        vre.y = sre[SMADDR(c + 1, row)]; vim.y = sim[SMADDR(c + 1, row)];
        vre.z = sre[SMADDR(c + 2, row)]; vim.z = sim[SMADDR(c + 2, row)];
        vre.w = sre[SMADDR(c + 3, row)]; vim.w = sim[SMADDR(c + 3, row)];
        *reinterpret_cast<float4*>(dr + g) = vre;
        *reinterpret_cast<float4*>(di + g) = vim;
    }
}

// ---------- row inverse FFT (in place on uifft) + complex abs ----------
__global__ void k_row_inv(float* __restrict__ uifft, float* __restrict__ cabs,
                          int bofs) {
    __shared__ float scr[8][512];
    __shared__ float t1r[256], t1i[256], t2r[256], t2i[256];
    int t = threadIdx.x, lane = t & 31, wp = t >> 5;
    t1r[t] = g_t1r_i[t]; t1i[t] = g_t1i_i[t];
    t2r[t] = g_t2r_i[t]; t2i[t] = g_t2i_i[t];
    __syncthreads();
    int row = blockIdx.x * 8 + wp, b = blockIdx.y + bofs;
    float* fr = uifft + (size_t)b * 2 * HWSZ + (size_t)row * WW;
    float* fi = fr + HWSZ;
    float* sc = scr[wp];
    float vr[8], vi[8];
#pragma unroll
    for (int j = 0; j < 8; j++) { vr[j] = fr[lane + 32 * j]; vi[j] = fi[lane + 32 * j]; }
#define RW_W(rw, nr, ni) { sc[SWZ(rw)] = nr; sc[256 + SWZ(rw)] = ni; }
#define RW_R(rw, or_, oi_) { or_ = sc[SWZ(rw)]; oi_ = sc[256 + SWZ(rw)]; }
    FFT256(1, 0, vr, vi, RW_R, RW_W, t1r, t1i, t2r, t2i);
    int d0l = ((lane >> 4) & 1) + (((lane >> 3) & 1) << 1);
    float* ap = cabs + (size_t)b * HWSZ + (size_t)row * WW;
#pragma unroll
    for (int j = 0; j < 8; j++) {
        int n = (lane & 7) + 8 * d0l + 32 * BRC[j];
        fr[n] = vr[j]; fi[n] = vi[j];
        ap[n] = sqrtf(vr[j] * vr[j] + vi[j] * vi[j]);
    }
#undef RW_W
#undef RW_R
}

extern "C" void kernel_launch(void* const* d_in, const int* in_sizes, int n_in,
                              void* d_out, int out_size) {
    const float* x = (const float*)d_in[0];
    const float* w = (const float*)d_in[1];
    if (n_in >= 2 && in_sizes[0] == HWSZ) {
        x = (const float*)d_in[1];
        w = (const float*)d_in[0];
    }
    float* out   = (float*)d_out;
    float* uifft = out + OFF_UIFFT;
    float* cabs  = out + OFF_ABS;
    float* mask  = out + OFF_MASK;
    float* fft   = out + OFF_FFT;
    float* uk    = out + OFF_UK;

    unsigned sk0, sk1;
    threefry2x32(0u, 42u, 0u, 1u, sk0, sk1);

    const int col_smem = (2 * 16 * CCP + 4 * 256) * (int)sizeof(float);   // 36864
    const int HB = BB / 2;   // 32 batches per stream

    static cudaStream_t s1 = 0, s2 = 0;
    static cudaEvent_t ev_fork = 0, ev_final = 0, ev_end = 0;
    static int inited = 0;
    if (!inited) {
        cudaStreamCreateWithFlags(&s1, cudaStreamNonBlocking);
        cudaStreamCreateWithFlags(&s2, cudaStreamNonBlocking);
        cudaEventCreateWithFlags(&ev_fork, cudaEventDisableTiming);
        cudaEventCreateWithFlags(&ev_final, cudaEventDisableTiming);
        cudaEventCreateWithFlags(&ev_end, cudaEventDisableTiming);
        cudaFuncSetAttribute(k_col, cudaFuncAttributeMaxDynamicSharedMemorySize, col_smem);
        inited = 1;
    }

    // fork: reduce+final on s1; row_fwd halves on main + s2
    cudaEventRecord(ev_fork, 0);
    cudaStreamWaitEvent(s1, ev_fork, 0);
    cudaStreamWaitEvent(s2, ev_fork, 0);
    k_reduce<<<64, 256, 0, s1>>>(w);
    k_final<<<1, 256, 0, s1>>>();
    cudaEventRecord(ev_final, s1);

    k_row_fwd<<<dim3(HH / 8, HB), 256>>>(x, fft, 0);
    k_row_fwd<<<dim3(HH / 8, HB), 256, 0, s2>>>(x, fft, HB);

    cudaStreamWaitEvent(0, ev_final, 0);
    cudaStreamWaitEvent(s2, ev_final, 0);

    k_col<<<dim3(WW / 16, HB), 256, col_smem>>>(fft, mask, uk, uifft, sk0, sk1, 0);
    k_col<<<dim3(WW / 16, HB), 256, col_smem, s2>>>(fft, mask, uk, uifft, sk0, sk1, HB);

    k_row_inv<<<dim3(HH / 8, HB), 256>>>(uifft, cabs, 0);
    k_row_inv<<<dim3(HH / 8, HB), 256, 0, s2>>>(uifft, cabs, HB);

    cudaEventRecord(ev_end, s2);
    cudaStreamWaitEvent(0, ev_end, 0);
}